// round 6
// baseline (speedup 1.0000x reference)
#include <cuda_runtime.h>
#include <cstdint>
#include <cstddef>

// Problem constants (fixed by the dataset)
#define B_   2
#define L_   2048
#define D_   1024
#define H_   16
#define DK_  64
#define LK_  2048
#define KSEL 1024   // topk = 0.5 * 2048

// ---------------------------------------------------------------------------
// Scratch (device globals; no dynamic allocation allowed)
// ---------------------------------------------------------------------------
__device__ float g_Q[B_ * H_ * L_ * DK_];            // 16 MB, [B,H,L,dk]
__device__ float g_K[B_ * H_ * L_ * DK_];            // 16 MB
__device__ float g_V[B_ * H_ * L_ * DK_];            // 16 MB
__device__ float g_S[(size_t)B_ * H_ * L_ * LK_];    // 512 MB, scores then probs
__device__ float g_C[B_ * L_ * D_];                  // 16 MB, ctx in [B,L,H*dk]

// ---------------------------------------------------------------------------
// Generic register-tiled GEMM: C = alpha * A x op(B) + bias
//   A: [M,K] row-major (ld = K)
//   TRANSB=true : B is [N,K] row-major, computes A @ B^T
//   TRANSB=false: B is [K,N] row-major, computes A @ B
// Per-batch (blockIdx.z) strides sA, sB, sC applied to A, B, C.
// MODE 0: store C[m*ldc + n]
// MODE 1: head-permute store (projection): m=b*L+l, n=h*64+d -> [B,H,L,dk]
// MODE 2: batched ctx store: per-z offset (z>>4)*L*D + (z&15)*64, C[m*ldc+n]
// Tile: 64x64x16, 256 threads, 4x4 microtile. All dims assumed divisible.
// ---------------------------------------------------------------------------
template <bool TRANSB, int MODE>
__global__ void __launch_bounds__(256) gemm_k(
    const float* __restrict__ Ag, const float* __restrict__ Bg,
    const float* __restrict__ bias, float* __restrict__ Cg,
    int M, int N, int K, float alpha,
    size_t sA, size_t sB, size_t sC, int ldc)
{
    const int BM = 64, BN = 64, BK = 16;
    __shared__ float As[BK][BM];
    __shared__ float Bs[BK][BN];

    int z = blockIdx.z;
    const float* A  = Ag + (size_t)z * sA;
    const float* Bp = Bg + (size_t)z * sB;
    float* C = Cg + (size_t)z * sC;
    if (MODE == 2)
        C = Cg + (size_t)(z >> 4) * ((size_t)L_ * D_) + (size_t)(z & 15) * DK_;

    int m0 = blockIdx.y * BM;
    int n0 = blockIdx.x * BN;
    int tid = threadIdx.x;
    int tx = tid & 15, ty = tid >> 4;

    float acc[4][4];
#pragma unroll
    for (int i = 0; i < 4; i++)
#pragma unroll
        for (int j = 0; j < 4; j++) acc[i][j] = 0.f;

    int aRow = tid >> 2;           // 0..63
    int aC4  = (tid & 3) * 4;      // 0..12

    for (int k0 = 0; k0 < K; k0 += BK) {
        // --- load A tile (transposed into smem) ---
        {
            float4 av = *(const float4*)(A + (size_t)(m0 + aRow) * K + k0 + aC4);
            As[aC4 + 0][aRow] = av.x;
            As[aC4 + 1][aRow] = av.y;
            As[aC4 + 2][aRow] = av.z;
            As[aC4 + 3][aRow] = av.w;
        }
        // --- load B tile ---
        if (TRANSB) {
            float4 bv = *(const float4*)(Bp + (size_t)(n0 + aRow) * K + k0 + aC4);
            Bs[aC4 + 0][aRow] = bv.x;
            Bs[aC4 + 1][aRow] = bv.y;
            Bs[aC4 + 2][aRow] = bv.z;
            Bs[aC4 + 3][aRow] = bv.w;
        } else {
            int bR  = tid >> 4;            // 0..15 (k)
            int bC4 = (tid & 15) * 4;      // 0..60 (n)
            float4 bv = *(const float4*)(Bp + (size_t)(k0 + bR) * N + n0 + bC4);
            *(float4*)&Bs[bR][bC4] = bv;
        }
        __syncthreads();

#pragma unroll
        for (int kk = 0; kk < BK; kk++) {
            float4 a4 = *(const float4*)&As[kk][ty * 4];
            float4 b4 = *(const float4*)&Bs[kk][tx * 4];
            float ar[4] = {a4.x, a4.y, a4.z, a4.w};
            float br[4] = {b4.x, b4.y, b4.z, b4.w};
#pragma unroll
            for (int i = 0; i < 4; i++)
#pragma unroll
                for (int j = 0; j < 4; j++)
                    acc[i][j] = fmaf(ar[i], br[j], acc[i][j]);
        }
        __syncthreads();
    }

#pragma unroll
    for (int i = 0; i < 4; i++) {
        int cm = m0 + ty * 4 + i;
#pragma unroll
        for (int j = 0; j < 4; j++) {
            int cn = n0 + tx * 4 + j;
            float v = acc[i][j] * alpha;
            if (bias) v += bias[cn];
            if (MODE == 1) {
                int b = cm >> 11, l = cm & (L_ - 1);
                int h = cn >> 6,  d = cn & (DK_ - 1);
                C[(((size_t)b * H_ + h) * L_ + l) * DK_ + d] = v;
            } else {
                C[(size_t)cm * ldc + cn] = v;
            }
        }
    }
}

// ---------------------------------------------------------------------------
// Exact top-k threshold + masked softmax, in place on score rows.
// One block (256 threads) per (b,h,q) row of 2048 scores.
// Algorithm: order-preserving uint keys; 4096-bin histogram on top 12 bits;
// suffix-scan to locate the k-th bin; gather in-bin candidates; exact rank
// among candidates -> exact threshold; softmax over {u >= thr}.
// ---------------------------------------------------------------------------
__device__ __forceinline__ unsigned fmono(float f) {
    unsigned u = __float_as_uint(f);
    return (u & 0x80000000u) ? ~u : (u | 0x80000000u);
}

__global__ void __launch_bounds__(256) select_softmax_k(float* __restrict__ S)
{
    __shared__ float    sv[LK_];        // 8 KB: raw scores, then exp values
    __shared__ unsigned hist[4096];     // 16 KB: histogram, reused as cand[]
    __shared__ unsigned chunk[256];
    __shared__ float    fred[8];
    __shared__ unsigned s_binid, s_cumabove, s_cnt, s_thr;
    __shared__ float    s_max, s_z;

    int tid  = threadIdx.x;
    int lane = tid & 31, w = tid >> 5;
    float* row = S + (size_t)blockIdx.x * LK_;

    for (int i = tid; i < 4096; i += 256) hist[i] = 0u;
    if (tid == 0) s_cnt = 0u;
    __syncthreads();

    // Pass 1: load, histogram, row max
    float mx = -3.4e38f;
    for (int j = tid; j < LK_; j += 256) {
        float f = row[j];
        sv[j] = f;
        unsigned u = fmono(f);
        atomicAdd(&hist[u >> 20], 1u);
        mx = fmaxf(mx, f);
    }
#pragma unroll
    for (int o = 16; o; o >>= 1) mx = fmaxf(mx, __shfl_xor_sync(0xffffffffu, mx, o));
    if (lane == 0) fred[w] = mx;
    __syncthreads();
    if (tid == 0) {
        float m = fred[0];
#pragma unroll
        for (int i = 1; i < 8; i++) m = fmaxf(m, fred[i]);
        s_max = m;
    }

    // Chunk sums (16 bins per thread), then inclusive suffix scan
    unsigned cs = 0;
#pragma unroll
    for (int b = 0; b < 16; b++) cs += hist[tid * 16 + b];
    chunk[tid] = cs;
    __syncthreads();
    for (int off = 1; off < 256; off <<= 1) {
        unsigned v = (tid + off < 256) ? chunk[tid + off] : 0u;
        __syncthreads();
        chunk[tid] += v;
        __syncthreads();
    }

    // Locate the bin containing the KSEL-th largest element
    {
        unsigned above = (tid + 1 < 256) ? chunk[tid + 1] : 0u; // elems in bins > this chunk
        unsigned incl  = chunk[tid];
        if (above < KSEL && incl >= KSEL) {
            unsigned cum = above;
            for (int b = tid * 16 + 15; b >= tid * 16; b--) {
                unsigned hb = hist[b];
                if (cum < KSEL && cum + hb >= KSEL) {
                    s_binid = (unsigned)b;
                    s_cumabove = cum;
                    break;
                }
                cum += hb;
            }
        }
    }
    __syncthreads();
    unsigned binid = s_binid;
    unsigned kk2   = KSEL - s_cumabove;   // rank of threshold within its bin
    __syncthreads();                      // hist reads done; safe to reuse as cand[]

    // Pass 2: gather candidates in the threshold bin
    for (int j = tid; j < LK_; j += 256) {
        unsigned u = fmono(sv[j]);
        if ((u >> 20) == binid) {
            unsigned idx = atomicAdd(&s_cnt, 1u);
            hist[idx] = u;
        }
    }
    __syncthreads();
    int c = (int)s_cnt;

    // Exact rank among candidates -> exact threshold key
    for (int i = tid; i < c; i += 256) {
        unsigned x = hist[i];
        int cg = 0, ce = 0;
        for (int j = 0; j < c; j++) {
            unsigned y = hist[j];
            cg += (y > x);
            ce += (y == x);
        }
        if (cg < (int)kk2 && cg + ce >= (int)kk2) s_thr = x;
    }
    __syncthreads();
    unsigned thr = s_thr;
    float m = s_max;

    // Pass 3: masked exp + sum
    float z = 0.f;
    for (int j = tid; j < LK_; j += 256) {
        float f = sv[j];
        unsigned u = fmono(f);
        float e = (u >= thr) ? __expf(f - m) : 0.f;
        sv[j] = e;
        z += e;
    }
#pragma unroll
    for (int o = 16; o; o >>= 1) z += __shfl_xor_sync(0xffffffffu, z, o);
    if (lane == 0) fred[w] = z;
    __syncthreads();
    if (tid == 0) {
        float t = 0.f;
#pragma unroll
        for (int i = 0; i < 8; i++) t += fred[i];
        s_z = t;
    }
    __syncthreads();
    float invz = 1.0f / s_z;

    // Pass 4: write normalized probabilities back
    for (int j = tid; j < LK_; j += 256) row[j] = sv[j] * invz;
}

// ---------------------------------------------------------------------------
// Launch
// ---------------------------------------------------------------------------
extern "C" void kernel_launch(void* const* d_in, const int* in_sizes, int n_in,
                              void* d_out, int out_size)
{
    const float* q  = (const float*)d_in[0];
    const float* k  = (const float*)d_in[1];
    const float* v  = (const float*)d_in[2];
    const float* Wq = (const float*)d_in[3];
    const float* bq = (const float*)d_in[4];
    const float* Wk = (const float*)d_in[5];
    const float* bk = (const float*)d_in[6];
    const float* Wv = (const float*)d_in[7];
    const float* bv = (const float*)d_in[8];
    const float* Wo = (const float*)d_in[9];
    const float* bo = (const float*)d_in[10];
    float* out = (float*)d_out;

    float *Qp, *Kp, *Vp, *Sp, *Cp;
    cudaGetSymbolAddress((void**)&Qp, g_Q);
    cudaGetSymbolAddress((void**)&Kp, g_K);
    cudaGetSymbolAddress((void**)&Vp, g_V);
    cudaGetSymbolAddress((void**)&Sp, g_S);
    cudaGetSymbolAddress((void**)&Cp, g_C);

    const int M = B_ * L_;   // 4096

    // 1) Projections: X @ W^T + b -> [B,H,L,dk]
    dim3 gp(D_ / 64, M / 64, 1);
    gemm_k<true, 1><<<gp, 256>>>(q, Wq, bq, Qp, M, D_, D_, 1.f, 0, 0, 0, D_);
    gemm_k<true, 1><<<gp, 256>>>(k, Wk, bk, Kp, M, D_, D_, 1.f, 0, 0, 0, D_);
    gemm_k<true, 1><<<gp, 256>>>(v, Wv, bv, Vp, M, D_, D_, 1.f, 0, 0, 0, D_);

    // 2) Scores: S = Q K^T / sqrt(dk), batched over (b,h)
    dim3 gs(LK_ / 64, L_ / 64, B_ * H_);
    gemm_k<true, 0><<<gs, 256>>>(Qp, Kp, nullptr, Sp, L_, LK_, DK_, 0.125f,
                                 (size_t)L_ * DK_, (size_t)L_ * DK_,
                                 (size_t)L_ * LK_, LK_);

    // 3) Exact top-1024 threshold + masked softmax (in place on S)
    select_softmax_k<<<B_ * H_ * L_, 256>>>(Sp);

    // 4) Ctx = P @ V, batched; store interleaved [B, L, H*dk]
    dim3 ga(DK_ / 64, L_ / 64, B_ * H_);
    gemm_k<false, 2><<<ga, 256>>>(Sp, Vp, nullptr, Cp, L_, DK_, LK_, 1.f,
                                  (size_t)L_ * LK_, (size_t)L_ * DK_, 0, D_);

    // 5) Output projection: Ctx @ Wo^T + bo
    gemm_k<true, 0><<<gp, 256>>>(Cp, Wo, bo, out, M, D_, D_, 1.f, 0, 0, 0, D_);
}

// round 10
// speedup vs baseline: 1.1471x; 1.1471x over previous
#include <cuda_runtime.h>
#include <cstdint>
#include <cstddef>

// Problem constants (fixed by the dataset)
#define B_   2
#define L_   2048
#define D_   1024
#define H_   16
#define DK_  64
#define LK_  2048
#define KSEL 1024   // topk = 0.5 * 2048

// ---------------------------------------------------------------------------
// Scratch (device globals; no dynamic allocation allowed)
// ---------------------------------------------------------------------------
__device__ float g_Q[B_ * H_ * L_ * DK_];            // 16 MB, [B,H,L,dk]
__device__ float g_K[B_ * H_ * L_ * DK_];            // 16 MB
__device__ float g_V[B_ * H_ * L_ * DK_];            // 16 MB
__device__ float g_S[(size_t)B_ * H_ * L_ * LK_];    // 512 MB, scores then probs
__device__ float g_C[B_ * L_ * D_];                  // 16 MB, ctx in [B,L,H*dk]

// ---------------------------------------------------------------------------
// Register-tiled fp32 GEMM, quadrant microtile.
//   C = alpha * A x op(B) + bias
//   A: [M,K] row-major.  TRANSB: B [N,K] (A@B^T) else B [K,N] (A@B).
//   Template tile: BM x BN x BK, microtile TM x TN (multiples of 4).
//   256 threads; thread (tx,ty) computes RQ x CQ quadrants of 4x4.
// MODE 0: C[m*ldc+n] (+ z*sC)
// MODE 1: head-permute store: m=b*2048+l, n=h*64+d -> [B,H,L,dk]
// MODE 2: batched ctx store: z -> (z>>4)*L*D + (z&15)*64, then C[m*ldc+n]
// ---------------------------------------------------------------------------
template <int BM, int BN, int BK, int TM, int TN, bool TRANSB, int MODE>
__global__ void __launch_bounds__(256) gemm2(
    const float* __restrict__ Ag, const float* __restrict__ Bg,
    const float* __restrict__ bias, float* __restrict__ Cg,
    int M, int N, int K, float alpha,
    size_t sA, size_t sB, size_t sC, int ldc)
{
    static_assert((BM / TM) * (BN / TN) == 256, "256 threads");
    constexpr int RQ = TM / 4;           // row quadrants
    constexpr int CQ = TN / 4;           // col quadrants
    constexpr int NT_N = BN / TN;        // threads along n

    __shared__ float As[BK][BM];
    __shared__ float Bs[BK][BN];

    int z = blockIdx.z;
    const float* A  = Ag + (size_t)z * sA;
    const float* Bp = Bg + (size_t)z * sB;
    float* C = Cg + (size_t)z * sC;
    if (MODE == 2)
        C = Cg + (size_t)(z >> 4) * ((size_t)L_ * D_) + (size_t)(z & 15) * DK_;

    int m0 = blockIdx.y * BM;
    int n0 = blockIdx.x * BN;
    int tid = threadIdx.x;
    int tx = tid % NT_N;
    int ty = tid / NT_N;

    float acc[TM][TN];
#pragma unroll
    for (int i = 0; i < TM; i++)
#pragma unroll
        for (int j = 0; j < TN; j++) acc[i][j] = 0.f;

    for (int k0 = 0; k0 < K; k0 += BK) {
        // ---- load A tile: BM x BK, store transposed As[k][m] ----
#pragma unroll
        for (int i = 0; i < (BM * BK) / 1024; i++) {
            int t   = tid + i * 256;
            int row = t / (BK / 4);
            int c4  = (t % (BK / 4)) * 4;
            float4 v = *(const float4*)(A + (size_t)(m0 + row) * K + k0 + c4);
            As[c4 + 0][row] = v.x;
            As[c4 + 1][row] = v.y;
            As[c4 + 2][row] = v.z;
            As[c4 + 3][row] = v.w;
        }
        // ---- load B tile ----
        if (TRANSB) {
            // B: [N,K]; tile BN x BK -> Bs[k][n]
#pragma unroll
            for (int i = 0; i < (BN * BK) / 1024; i++) {
                int t   = tid + i * 256;
                int row = t / (BK / 4);
                int c4  = (t % (BK / 4)) * 4;
                float4 v = *(const float4*)(Bp + (size_t)(n0 + row) * K + k0 + c4);
                Bs[c4 + 0][row] = v.x;
                Bs[c4 + 1][row] = v.y;
                Bs[c4 + 2][row] = v.z;
                Bs[c4 + 3][row] = v.w;
            }
        } else {
            // B: [K,N]; tile BK x BN -> Bs[k][n] directly (float4 stores)
#pragma unroll
            for (int i = 0; i < (BK * BN) / 1024; i++) {
                int t   = tid + i * 256;
                int row = t / (BN / 4);
                int c4  = (t % (BN / 4)) * 4;
                float4 v = *(const float4*)(Bp + (size_t)(k0 + row) * N + n0 + c4);
                *(float4*)&Bs[row][c4] = v;
            }
        }
        __syncthreads();

        // ---- compute ----
#pragma unroll
        for (int kk = 0; kk < BK; kk++) {
            float a[TM], b[TN];
#pragma unroll
            for (int q = 0; q < RQ; q++)
                *(float4*)&a[q * 4] = *(const float4*)&As[kk][ty * 4 + q * (BM / RQ)];
#pragma unroll
            for (int q = 0; q < CQ; q++)
                *(float4*)&b[q * 4] = *(const float4*)&Bs[kk][tx * 4 + q * (BN / CQ)];
#pragma unroll
            for (int i = 0; i < TM; i++)
#pragma unroll
                for (int j = 0; j < TN; j++)
                    acc[i][j] = fmaf(a[i], b[j], acc[i][j]);
        }
        __syncthreads();
    }

    // ---- store ----
#pragma unroll
    for (int qm = 0; qm < RQ; qm++) {
#pragma unroll
        for (int i = 0; i < 4; i++) {
            int cm = m0 + ty * 4 + qm * (BM / RQ) + i;
#pragma unroll
            for (int qn = 0; qn < CQ; qn++) {
#pragma unroll
                for (int j = 0; j < 4; j++) {
                    int cn = n0 + tx * 4 + qn * (BN / CQ) + j;
                    float v = acc[qm * 4 + i][qn * 4 + j] * alpha;
                    if (bias) v += bias[cn];
                    if (MODE == 1) {
                        int b = cm >> 11, l = cm & (L_ - 1);
                        int h = cn >> 6,  d = cn & (DK_ - 1);
                        C[(((size_t)b * H_ + h) * L_ + l) * DK_ + d] = v;
                    } else {
                        C[(size_t)cm * ldc + cn] = v;
                    }
                }
            }
        }
    }
}

// ---------------------------------------------------------------------------
// Exact top-k threshold + masked softmax, in place on score rows.
// One block (256 threads) per (b,h,q) row of 2048 scores.
// ---------------------------------------------------------------------------
__device__ __forceinline__ unsigned fmono(float f) {
    unsigned u = __float_as_uint(f);
    return (u & 0x80000000u) ? ~u : (u | 0x80000000u);
}

__global__ void __launch_bounds__(256) select_softmax_k(float* __restrict__ S)
{
    __shared__ float    sv[LK_];        // 8 KB: raw scores, then exp values
    __shared__ unsigned hist[4096];     // 16 KB: histogram, reused as cand[]
    __shared__ unsigned chunk[256];
    __shared__ float    fred[8];
    __shared__ unsigned s_binid, s_cumabove, s_cnt, s_thr;
    __shared__ float    s_max, s_z;

    int tid  = threadIdx.x;
    int lane = tid & 31, w = tid >> 5;
    float* row = S + (size_t)blockIdx.x * LK_;

    for (int i = tid; i < 4096; i += 256) hist[i] = 0u;
    if (tid == 0) s_cnt = 0u;
    __syncthreads();

    // Pass 1: load, histogram, row max
    float mx = -3.4e38f;
    for (int j = tid; j < LK_; j += 256) {
        float f = row[j];
        sv[j] = f;
        unsigned u = fmono(f);
        atomicAdd(&hist[u >> 20], 1u);
        mx = fmaxf(mx, f);
    }
#pragma unroll
    for (int o = 16; o; o >>= 1) mx = fmaxf(mx, __shfl_xor_sync(0xffffffffu, mx, o));
    if (lane == 0) fred[w] = mx;
    __syncthreads();
    if (tid == 0) {
        float m = fred[0];
#pragma unroll
        for (int i = 1; i < 8; i++) m = fmaxf(m, fred[i]);
        s_max = m;
    }

    // Chunk sums (16 bins per thread), then inclusive suffix scan
    unsigned cs = 0;
#pragma unroll
    for (int b = 0; b < 16; b++) cs += hist[tid * 16 + b];
    chunk[tid] = cs;
    __syncthreads();
    for (int off = 1; off < 256; off <<= 1) {
        unsigned v = (tid + off < 256) ? chunk[tid + off] : 0u;
        __syncthreads();
        chunk[tid] += v;
        __syncthreads();
    }

    // Locate the bin containing the KSEL-th largest element
    {
        unsigned above = (tid + 1 < 256) ? chunk[tid + 1] : 0u;
        unsigned incl  = chunk[tid];
        if (above < KSEL && incl >= KSEL) {
            unsigned cum = above;
            for (int b = tid * 16 + 15; b >= tid * 16; b--) {
                unsigned hb = hist[b];
                if (cum < KSEL && cum + hb >= KSEL) {
                    s_binid = (unsigned)b;
                    s_cumabove = cum;
                    break;
                }
                cum += hb;
            }
        }
    }
    __syncthreads();
    unsigned binid = s_binid;
    unsigned kk2   = KSEL - s_cumabove;   // rank of threshold within its bin
    __syncthreads();                      // hist reads done; reuse as cand[]

    // Pass 2: gather candidates in the threshold bin
    for (int j = tid; j < LK_; j += 256) {
        unsigned u = fmono(sv[j]);
        if ((u >> 20) == binid) {
            unsigned idx = atomicAdd(&s_cnt, 1u);
            hist[idx] = u;
        }
    }
    __syncthreads();
    int c = (int)s_cnt;

    // Exact rank among candidates -> exact threshold key
    for (int i = tid; i < c; i += 256) {
        unsigned x = hist[i];
        int cg = 0, ce = 0;
        for (int j = 0; j < c; j++) {
            unsigned y = hist[j];
            cg += (y > x);
            ce += (y == x);
        }
        if (cg < (int)kk2 && cg + ce >= (int)kk2) s_thr = x;
    }
    __syncthreads();
    unsigned thr = s_thr;
    float m = s_max;

    // Pass 3: masked exp + sum
    float z = 0.f;
    for (int j = tid; j < LK_; j += 256) {
        float f = sv[j];
        unsigned u = fmono(f);
        float e = (u >= thr) ? __expf(f - m) : 0.f;
        sv[j] = e;
        z += e;
    }
#pragma unroll
    for (int o = 16; o; o >>= 1) z += __shfl_xor_sync(0xffffffffu, z, o);
    if (lane == 0) fred[w] = z;
    __syncthreads();
    if (tid == 0) {
        float t = 0.f;
#pragma unroll
        for (int i = 0; i < 8; i++) t += fred[i];
        s_z = t;
    }
    __syncthreads();
    float invz = 1.0f / s_z;

    // Pass 4: write normalized probabilities back
    for (int j = tid; j < LK_; j += 256) row[j] = sv[j] * invz;
}

// ---------------------------------------------------------------------------
// Launch
// ---------------------------------------------------------------------------
extern "C" void kernel_launch(void* const* d_in, const int* in_sizes, int n_in,
                              void* d_out, int out_size)
{
    const float* q  = (const float*)d_in[0];
    const float* k  = (const float*)d_in[1];
    const float* v  = (const float*)d_in[2];
    const float* Wq = (const float*)d_in[3];
    const float* bq = (const float*)d_in[4];
    const float* Wk = (const float*)d_in[5];
    const float* bk = (const float*)d_in[6];
    const float* Wv = (const float*)d_in[7];
    const float* bv = (const float*)d_in[8];
    const float* Wo = (const float*)d_in[9];
    const float* bo = (const float*)d_in[10];
    float* out = (float*)d_out;

    float *Qp, *Kp, *Vp, *Sp, *Cp;
    cudaGetSymbolAddress((void**)&Qp, g_Q);
    cudaGetSymbolAddress((void**)&Kp, g_K);
    cudaGetSymbolAddress((void**)&Vp, g_V);
    cudaGetSymbolAddress((void**)&Sp, g_S);
    cudaGetSymbolAddress((void**)&Cp, g_C);

    const int M = B_ * L_;   // 4096

    // 1) Projections: X @ W^T + b -> [B,H,L,dk]   (128x128x8, 8x8 microtile)
    dim3 gp(D_ / 128, M / 128, 1);
    gemm2<128,128,8,8,8,true,1><<<gp, 256>>>(q, Wq, bq, Qp, M, D_, D_, 1.f, 0, 0, 0, D_);
    gemm2<128,128,8,8,8,true,1><<<gp, 256>>>(k, Wk, bk, Kp, M, D_, D_, 1.f, 0, 0, 0, D_);
    gemm2<128,128,8,8,8,true,1><<<gp, 256>>>(v, Wv, bv, Vp, M, D_, D_, 1.f, 0, 0, 0, D_);

    // 2) Scores: S = Q K^T / sqrt(dk), batched over (b,h)
    dim3 gs(LK_ / 128, L_ / 128, B_ * H_);
    gemm2<128,128,8,8,8,true,0><<<gs, 256>>>(Qp, Kp, nullptr, Sp, L_, LK_, DK_, 0.125f,
                                             (size_t)L_ * DK_, (size_t)L_ * DK_,
                                             (size_t)L_ * LK_, LK_);

    // 3) Exact top-1024 threshold + masked softmax (in place on S)
    select_softmax_k<<<B_ * H_ * L_, 256>>>(Sp);

    // 4) Ctx = P @ V, batched; store interleaved [B, L, H*dk]  (128x64x16, 8x4)
    dim3 ga(1, L_ / 128, B_ * H_);
    gemm2<128,64,16,8,4,false,2><<<ga, 256>>>(Sp, Vp, nullptr, Cp, L_, DK_, LK_, 1.f,
                                              (size_t)L_ * LK_, (size_t)L_ * DK_, 0, D_);

    // 5) Output projection: Ctx @ Wo^T + bo
    gemm2<128,128,8,8,8,true,0><<<gp, 256>>>(Cp, Wo, bo, out, M, D_, D_, 1.f, 0, 0, 0, D_);
}